// round 2
// baseline (speedup 1.0000x reference)
#include <cuda_runtime.h>
#include <math_constants.h>

#define N_SRC 100000
#define MROWS 20000
#define KNEI 32
#define HDIM 128
#define NEG_SLOPE 0.01f
#define FULLM 0xffffffffu

// ---------------------------------------------------------------------------
// Single fused kernel. One warp per row m; 8 warps / block; 2500 blocks.
//
// Math: h(x)_j = relu(x*wl_j + bl_j). With wl,bl >= 0 and j sorted by
// r_j = bl_j/wl_j descending, the active set {j : x*wl_j + bl_j > 0} is the
// prefix of length c(x) = #{j : r_j > -x}. Hence for any weight vector v:
//   sum_j relu(x*wl_j+bl_j) * v_j = x * PA_v[c] + PB_v[c]
// with PA_v/PB_v prefix sums of (wl_j*v_j, bl_j*v_j) in sorted order.
// Used with v = a_nei (row-independent, for logits) and v = hr_m (per-row).
// ---------------------------------------------------------------------------
__global__ void __launch_bounds__(256) fused_kernel(
        const int*   __restrict__ nei,
        const float* __restrict__ h,
        const float* __restrict__ h_refer,
        const float* __restrict__ wl_g, const float* __restrict__ bl_g,
        const float* __restrict__ wr_g, const float* __restrict__ br_g,
        const float* __restrict__ att_inter,
        float* __restrict__ out, float* __restrict__ attOut) {

    __shared__ float  s_rraw[HDIM];        // unsorted ratios (for ranking)
    __shared__ float  s_r[HDIM];           // sorted ratios, descending
    __shared__ float2 s_wlbl[HDIM];        // (wl, bl) permuted
    __shared__ float2 s_wrbr[HDIM];        // (wr, br) permuted
    __shared__ float  s_aref[HDIM];        // a_ref permuted
    __shared__ float2 s_fab[HDIM];         // (wl*a_nei, bl*a_nei) permuted
    __shared__ float4 s_pref[8][HDIM + 1]; // per-warp prefix: (A_hr,B_hr,A_f,B_f)

    int tid  = threadIdx.x;
    int warp = tid >> 5, lane = tid & 31;

    // ---- per-block param sort (128 threads) ----
    float w, b, r, wr, br, aref, fa, fb;
    if (tid < HDIM) {
        w = wl_g[tid]; b = bl_g[tid];
        if (w > 0.f) r = b / w;
        else         r = (b > 0.f) ? CUDART_INF_F : -CUDART_INF_F;
        s_rraw[tid] = r;
        wr = wr_g[tid]; br = br_g[tid];
        aref = att_inter[tid];
        float an = att_inter[HDIM + tid];
        fa = w * an; fb = b * an;
    }
    __syncthreads();
    if (tid < HDIM) {
        int rank = 0;
        #pragma unroll 8
        for (int k = 0; k < HDIM; k++) {
            float rk = s_rraw[k];
            rank += (rk > r) || (rk == r && k < tid);   // stable descending
        }
        s_r[rank]    = r;
        s_wlbl[rank] = make_float2(w, b);
        s_wrbr[rank] = make_float2(wr, br);
        s_aref[rank] = aref;
        s_fab[rank]  = make_float2(fa, fb);
    }
    __syncthreads();

    int m = blockIdx.x * 8 + warp;
    float y = h_refer[m];

    // ---- per-row hr + joint 4-channel scan (a,b = hr-weighted; c,d = f) ----
    float a[4], bb[4], fc[4], fd[4];
    float gp = 0.f;
    #pragma unroll
    for (int i = 0; i < 4; i++) {            // lane owns contiguous j = 4*lane+i
        int j = lane * 4 + i;
        float2 wr2 = s_wrbr[j];
        float hr = fmaxf(fmaf(y, wr2.x, wr2.y), 0.f);
        gp = fmaf(hr, s_aref[j], gp);        // g_m = hr . a_ref
        float2 wl2 = s_wlbl[j];
        a[i]  = wl2.x * hr;
        bb[i] = wl2.y * hr;
        float2 f2 = s_fab[j];
        fc[i] = f2.x;
        fd[i] = f2.y;
    }
    // local inclusive scans
    #pragma unroll
    for (int i = 1; i < 4; i++) {
        a[i] += a[i-1]; bb[i] += bb[i-1]; fc[i] += fc[i-1]; fd[i] += fd[i-1];
    }
    // warp scan of lane totals (4 channels)
    float ta = a[3], tb = bb[3], tc = fc[3], td = fd[3];
    #pragma unroll
    for (int o = 1; o < 32; o <<= 1) {
        float va = __shfl_up_sync(FULLM, ta, o);
        float vb = __shfl_up_sync(FULLM, tb, o);
        float vc = __shfl_up_sync(FULLM, tc, o);
        float vd = __shfl_up_sync(FULLM, td, o);
        if (lane >= o) { ta += va; tb += vb; tc += vc; td += vd; }
    }
    float oa = ta - a[3], ob = tb - bb[3], oc = tc - fc[3], od = td - fd[3];
    if (lane == 0) s_pref[warp][0] = make_float4(0.f, 0.f, 0.f, 0.f);
    #pragma unroll
    for (int i = 0; i < 4; i++)
        s_pref[warp][lane * 4 + i + 1] =
            make_float4(oa + a[i], ob + bb[i], oc + fc[i], od + fd[i]);

    #pragma unroll
    for (int o = 16; o; o >>= 1) gp += __shfl_xor_sync(FULLM, gp, o);  // bcast g
    __syncwarp();   // order s_pref stores before random reads below

    // ---- lane = neighbor k ----
    int idx = nei[m * KNEI + lane];
    float x = __ldg(&h[idx]);                // 400KB array -> L2 resident

    // c = #{j : r_j > -x}  (binary search on descending s_r; 7 steps)
    float t = -x;
    int lo = 0, hi = HDIM;
    #pragma unroll
    for (int step = 0; step < 7; step++) {
        int mid = (lo + hi) >> 1;
        if (s_r[mid] > t) lo = mid + 1; else hi = mid;
    }
    float4 p = s_pref[warp][lo];
    float lr = fmaf(x, p.x, p.y);            // nei_emb . hr
    float f  = fmaf(x, p.z, p.w);            // nei_emb . a_nei

    float logit = gp + f;
    logit = (logit >= 0.f) ? logit : NEG_SLOPE * logit;

    // softmax over 32 lanes (max-subtracted, like jax.nn.softmax)
    float mx = logit;
    #pragma unroll
    for (int o = 16; o; o >>= 1) mx = fmaxf(mx, __shfl_xor_sync(FULLM, mx, o));
    float e = __expf(logit - mx);
    float s = e;
    #pragma unroll
    for (int o = 16; o; o >>= 1) s += __shfl_xor_sync(FULLM, s, o);
    float att = e / s;

    float acc = att * lr;
    #pragma unroll
    for (int o = 16; o; o >>= 1) acc += __shfl_xor_sync(FULLM, acc, o);

    if (lane == 0) out[m] = fmaxf(acc, 0.f);
    attOut[m * KNEI + lane] = att;
}

// ---------------------------------------------------------------------------
extern "C" void kernel_launch(void* const* d_in, const int* in_sizes, int n_in,
                              void* d_out, int out_size) {
    const int*   nei       = (const int*)  d_in[0];
    const float* h         = (const float*)d_in[1];
    const float* h_refer   = (const float*)d_in[2];
    const float* map_l_w   = (const float*)d_in[3];
    const float* map_l_b   = (const float*)d_in[4];
    const float* map_r_w   = (const float*)d_in[5];
    const float* map_r_b   = (const float*)d_in[6];
    const float* att_inter = (const float*)d_in[7];

    float* out    = (float*)d_out;          // [M]
    float* attOut = out + MROWS;            // [M, K] flattened after out

    fused_kernel<<<MROWS / 8, 256>>>(nei, h, h_refer,
                                     map_l_w, map_l_b, map_r_w, map_r_b,
                                     att_inter, out, attOut);
}

// round 3
// speedup vs baseline: 1.3094x; 1.3094x over previous
#include <cuda_runtime.h>
#include <math_constants.h>

#define N_SRC 100000
#define MROWS 20000
#define KNEI 32
#define HDIM 128
#define RPW 4            // rows per warp
#define WPB 8            // warps per block
#define NEG_SLOPE 0.01f
#define FULLM 0xffffffffu

// ---------------------------------------------------------------------------
// One fused kernel, 625 blocks x 256 threads, 4 rows per warp.
//
// Piecewise-linear-prefix identity: with wl,bl >= 0 and j sorted by
// r_j = bl_j/wl_j descending, {j : x*wl_j+bl_j > 0} is a prefix of length
// c(x) = #{j : r_j > -x}.  So for any v:  sum_j relu(x wl_j + bl_j) v_j
//   = x * PA_v[c] + PB_v[c].
// v = a_nei  -> row-independent table s_F          (logit term f)
// v = hr_m   -> per-row; but hr_j = relu(y wr_j + br_j) with wr,br >= 0, so
//   y >= 0  => hr_j = y wr_j + br_j exactly  => lr uses row-independent s_P
//   y <  0  => 2-channel per-row warp scan fallback
// ---------------------------------------------------------------------------
__global__ void __launch_bounds__(256) fused_kernel(
        const int*   __restrict__ nei,
        const float* __restrict__ h,
        const float* __restrict__ h_refer,
        const float* __restrict__ wl_g, const float* __restrict__ bl_g,
        const float* __restrict__ wr_g, const float* __restrict__ br_g,
        const float* __restrict__ att_inter,
        float* __restrict__ out, float* __restrict__ attOut) {

    __shared__ float  s_rraw[HDIM];
    __shared__ float  s_r[HDIM];            // sorted ratios, descending
    __shared__ float4 s_scat4[HDIM];        // scattered (wlwr, wlbr, blwr, blbr)
    __shared__ float2 s_scat2[HDIM];        // scattered (wl*a_nei, bl*a_nei)
    __shared__ float2 s_wlbl[HDIM];         // permuted (wl, bl)  (scan path)
    __shared__ float2 s_wrbr[HDIM];         // permuted (wr, br)  (scan path)
    __shared__ float  s_aref[HDIM];         // permuted a_ref     (scan path)
    __shared__ float4 s_P[HDIM + 1];        // prefix of scat4
    __shared__ float2 s_F[HDIM + 1];        // prefix of scat2
    __shared__ float2 s_pref[WPB][HDIM + 1];// per-warp scan result (y<0 path)
    __shared__ float  s_wt[4][6];           // cross-warp scan totals
    __shared__ float  s_cw[4][2];           // c1/c2 warp partials
    __shared__ float2 s_c12;                // (sum wr*aref, sum br*aref)

    const int tid  = threadIdx.x;
    const int warp = tid >> 5, lane = tid & 31;

    // ================= prologue (once per block) =================
    float r = 0.f, v0, v1, v2, v3, v4, v5, cw1, cw2;
    float pw, pb, pwr, pbr, par;
    if (tid < HDIM) {
        pw  = wl_g[tid];  pb  = bl_g[tid];
        pwr = wr_g[tid];  pbr = br_g[tid];
        par = att_inter[tid];
        float an = att_inter[HDIM + tid];
        if (pw > 0.f) r = pb / pw;
        else          r = (pb > 0.f) ? CUDART_INF_F : -CUDART_INF_F;
        s_rraw[tid] = r;
        v0 = pw * pwr;  v1 = pw * pbr;      // wl*wr, wl*br
        v2 = pb * pwr;  v3 = pb * pbr;      // bl*wr, bl*br
        v4 = pw * an;   v5 = pb * an;       // wl*a_nei, bl*a_nei
        cw1 = pwr * par; cw2 = pbr * par;
    }
    __syncthreads();
    if (tid < HDIM) {
        int rank = 0;
        #pragma unroll 8
        for (int k = 0; k < HDIM; k++) {
            float rk = s_rraw[k];
            rank += (rk > r) || (rk == r && k < tid);   // stable descending
        }
        s_r[rank]     = r;
        s_scat4[rank] = make_float4(v0, v1, v2, v3);
        s_scat2[rank] = make_float2(v4, v5);
        s_wlbl[rank]  = make_float2(pw, pb);
        s_wrbr[rank]  = make_float2(pwr, pbr);
        s_aref[rank]  = par;
        // c1/c2: butterfly within each quarter-warp group -> warp partials
        #pragma unroll
        for (int o = 16; o; o >>= 1) {
            cw1 += __shfl_xor_sync(FULLM, cw1, o);
            cw2 += __shfl_xor_sync(FULLM, cw2, o);
        }
        if (lane == 0) { s_cw[warp][0] = cw1; s_cw[warp][1] = cw2; }
    }
    __syncthreads();
    if (tid < HDIM) {
        // inclusive 6-channel scan over the SORTED arrays
        float4 q4 = s_scat4[tid];
        float2 q2 = s_scat2[tid];
        float a0 = q4.x, a1 = q4.y, a2 = q4.z, a3 = q4.w, a4 = q2.x, a5 = q2.y;
        #pragma unroll
        for (int o = 1; o < 32; o <<= 1) {
            float t0 = __shfl_up_sync(FULLM, a0, o);
            float t1 = __shfl_up_sync(FULLM, a1, o);
            float t2 = __shfl_up_sync(FULLM, a2, o);
            float t3 = __shfl_up_sync(FULLM, a3, o);
            float t4 = __shfl_up_sync(FULLM, a4, o);
            float t5 = __shfl_up_sync(FULLM, a5, o);
            if (lane >= o) { a0 += t0; a1 += t1; a2 += t2; a3 += t3; a4 += t4; a5 += t5; }
        }
        if (lane == 31) {
            s_wt[warp][0] = a0; s_wt[warp][1] = a1; s_wt[warp][2] = a2;
            s_wt[warp][3] = a3; s_wt[warp][4] = a4; s_wt[warp][5] = a5;
        }
        // stash inclusive values temporarily in scat arrays
        s_scat4[tid] = make_float4(a0, a1, a2, a3);
        s_scat2[tid] = make_float2(a4, a5);
    }
    __syncthreads();
    if (tid < HDIM) {
        float o0 = 0.f, o1 = 0.f, o2 = 0.f, o3 = 0.f, o4 = 0.f, o5 = 0.f;
        for (int w = 0; w < warp; w++) {
            o0 += s_wt[w][0]; o1 += s_wt[w][1]; o2 += s_wt[w][2];
            o3 += s_wt[w][3]; o4 += s_wt[w][4]; o5 += s_wt[w][5];
        }
        float4 q4 = s_scat4[tid];
        float2 q2 = s_scat2[tid];
        s_P[tid + 1] = make_float4(q4.x + o0, q4.y + o1, q4.z + o2, q4.w + o3);
        s_F[tid + 1] = make_float2(q2.x + o4, q2.y + o5);
        if (tid == 0) {
            s_P[0] = make_float4(0.f, 0.f, 0.f, 0.f);
            s_F[0] = make_float2(0.f, 0.f);
            s_c12  = make_float2(s_cw[0][0] + s_cw[1][0] + s_cw[2][0] + s_cw[3][0],
                                 s_cw[0][1] + s_cw[1][1] + s_cw[2][1] + s_cw[3][1]);
        }
    }
    __syncthreads();

    // per-lane params for the y<0 scan path (lane owns j = 4*lane+i)
    float pwl[4], pbl[4], pwr2[4], pbr2[4], parf[4];
    #pragma unroll
    for (int i = 0; i < 4; i++) {
        int j = lane * 4 + i;
        float2 t = s_wlbl[j]; pwl[i] = t.x;  pbl[i] = t.y;
        float2 u = s_wrbr[j]; pwr2[i] = u.x; pbr2[i] = u.y;
        parf[i] = s_aref[j];
    }
    const float c1 = s_c12.x, c2 = s_c12.y;

    // ================= main: RPW rows per warp =================
    const int mbase = (blockIdx.x * WPB + warp) * RPW;

    #pragma unroll 1
    for (int rr = 0; rr < RPW; rr++) {
        int m = mbase + rr;
        float y = __ldg(&h_refer[m]);
        int  idx = nei[m * KNEI + lane];
        float x = __ldg(&h[idx]);             // 400KB table, L2-resident

        // c = #{j : r_j > -x}  (7-step binary search on descending s_r)
        float t = -x;
        int lo = 0, hi = HDIM;
        #pragma unroll
        for (int s = 0; s < 7; s++) {
            int mid = (lo + hi) >> 1;
            if (s_r[mid] > t) lo = mid + 1; else hi = mid;
        }
        float2 F = s_F[lo];
        float f = fmaf(x, F.x, F.y);          // nei_emb . a_nei

        float gp, lr;
        if (y >= 0.f) {
            // hr_j = y*wr_j + br_j exactly -> row-independent tables
            gp = fmaf(y, c1, c2);
            float4 P = s_P[lo];
            lr = fmaf(x, fmaf(y, P.x, P.y), fmaf(y, P.z, P.w));
        } else {
            // fallback: per-row 2-channel prefix of (wl*hr, bl*hr)
            float a[4], b[4];
            gp = 0.f;
            #pragma unroll
            for (int i = 0; i < 4; i++) {
                float hr = fmaxf(fmaf(y, pwr2[i], pbr2[i]), 0.f);
                gp = fmaf(hr, parf[i], gp);
                a[i] = pwl[i] * hr;
                b[i] = pbl[i] * hr;
            }
            a[1] += a[0]; a[2] += a[1]; a[3] += a[2];
            b[1] += b[0]; b[2] += b[1]; b[3] += b[2];
            float ta = a[3], tb = b[3];
            #pragma unroll
            for (int o = 1; o < 32; o <<= 1) {
                float va = __shfl_up_sync(FULLM, ta, o);
                float vb = __shfl_up_sync(FULLM, tb, o);
                if (lane >= o) { ta += va; tb += vb; }
            }
            float oa = ta - a[3], ob = tb - b[3];
            if (lane == 0) s_pref[warp][0] = make_float2(0.f, 0.f);
            #pragma unroll
            for (int i = 0; i < 4; i++)
                s_pref[warp][lane * 4 + i + 1] = make_float2(oa + a[i], ob + b[i]);
            #pragma unroll
            for (int o = 16; o; o >>= 1) gp += __shfl_xor_sync(FULLM, gp, o);
            __syncwarp();
            float2 p = s_pref[warp][lo];
            lr = fmaf(x, p.x, p.y);
            __syncwarp();   // reads done before next row's stores
        }

        float logit = gp + f;
        logit = (logit >= 0.f) ? logit : NEG_SLOPE * logit;

        // warp softmax over 32 neighbors
        float mx = logit;
        #pragma unroll
        for (int o = 16; o; o >>= 1) mx = fmaxf(mx, __shfl_xor_sync(FULLM, mx, o));
        float e = __expf(logit - mx);
        float sden = e;
        #pragma unroll
        for (int o = 16; o; o >>= 1) sden += __shfl_xor_sync(FULLM, sden, o);
        float att = e / sden;

        float acc = att * lr;
        #pragma unroll
        for (int o = 16; o; o >>= 1) acc += __shfl_xor_sync(FULLM, acc, o);

        if (lane == 0) out[m] = fmaxf(acc, 0.f);
        attOut[m * KNEI + lane] = att;
    }
}

// ---------------------------------------------------------------------------
extern "C" void kernel_launch(void* const* d_in, const int* in_sizes, int n_in,
                              void* d_out, int out_size) {
    const int*   nei       = (const int*)  d_in[0];
    const float* h         = (const float*)d_in[1];
    const float* h_refer   = (const float*)d_in[2];
    const float* map_l_w   = (const float*)d_in[3];
    const float* map_l_b   = (const float*)d_in[4];
    const float* map_r_w   = (const float*)d_in[5];
    const float* map_r_b   = (const float*)d_in[6];
    const float* att_inter = (const float*)d_in[7];

    float* out    = (float*)d_out;          // [M]
    float* attOut = out + MROWS;            // [M, K]

    fused_kernel<<<MROWS / (WPB * RPW), 256>>>(nei, h, h_refer,
                                               map_l_w, map_l_b, map_r_w, map_r_b,
                                               att_inter, out, attOut);
}

// round 6
// speedup vs baseline: 1.3249x; 1.0118x over previous
#include <cuda_runtime.h>
#include <math_constants.h>

#define N_SRC 100000
#define MROWS 20000
#define KNEI 32
#define HDIM 128
#define RPW 4            // rows per warp
#define WPB 8            // warps per block
#define NEG_SLOPE 0.01f
#define FULLM 0xffffffffu

// exact fp32 warp max via integer redux (monotone order-preserving map)
__device__ __forceinline__ float warp_max_f32(float x) {
    int ix = __float_as_int(x);
    ix = (ix >= 0) ? ix : (ix ^ 0x7fffffff);
    int mi;
    asm("redux.sync.max.s32 %0, %1, 0xffffffff;" : "=r"(mi) : "r"(ix));
    return __int_as_float((mi >= 0) ? mi : (mi ^ 0x7fffffff));
}

// ---------------------------------------------------------------------------
// One fused kernel, 625 blocks x 256 threads, 4 rows per warp.
//
// Piecewise-linear-prefix identity: with wl,bl >= 0 and j sorted by
// r_j = bl_j/wl_j descending, {j : x*wl_j+bl_j > 0} is a prefix of length
// c(x) = #{j : r_j > -x}.  So for any v:  sum_j relu(x wl_j + bl_j) v_j
//   = x * PA_v[c] + PB_v[c].
// v = a_nei -> row-independent table s_F.  v = hr_m -> per-row, but
//   y >= 0 (wr,br>=0) => hr_j = y wr_j + br_j exactly => row-indep table s_P
//   y <  0 => 3-channel warp-scan fallback (a, b, gp).
// ---------------------------------------------------------------------------
__global__ void __launch_bounds__(256) fused_kernel(
        const int*   __restrict__ nei,
        const float* __restrict__ h,
        const float* __restrict__ h_refer,
        const float* __restrict__ wl_g, const float* __restrict__ bl_g,
        const float* __restrict__ wr_g, const float* __restrict__ br_g,
        const float* __restrict__ att_inter,
        float* __restrict__ out, float* __restrict__ attOut) {

    __shared__ __align__(16) float s_rraw[HDIM];
    __shared__ float  s_r[HDIM];            // sorted ratios, descending
    __shared__ float4 s_scat4[HDIM];        // (wlwr, wlbr, blwr, blbr) permuted
    __shared__ float2 s_scat2[HDIM];        // (wl*a_nei, bl*a_nei) permuted
    __shared__ float2 s_wlbl[HDIM];         // permuted (wl, bl)  (scan path)
    __shared__ float2 s_wrbr[HDIM];         // permuted (wr, br)  (scan path)
    __shared__ float  s_aref[HDIM];         // permuted a_ref     (scan path)
    __shared__ float4 s_P[HDIM + 1];        // prefix of scat4
    __shared__ float2 s_F[HDIM + 1];        // prefix of scat2
    __shared__ float2 s_pref[WPB][HDIM + 1];// per-warp scan table (y<0 path)
    __shared__ float  s_wt[4][6];           // cross-warp scan totals
    __shared__ float  s_cw[4][2];           // c1/c2 warp partials
    __shared__ float2 s_c12;                // (sum wr*aref, sum br*aref)

    const int tid  = threadIdx.x;
    const int warp = tid >> 5, lane = tid & 31;
    const int mbase = (blockIdx.x * WPB + warp) * RPW;

    // ---- prefetch all row data BEFORE the prologue (hides gather latency) --
    int   idxv[RPW];
    float xv[RPW], yv[RPW];
    #pragma unroll
    for (int rr = 0; rr < RPW; rr++)
        idxv[rr] = __ldg(&nei[(mbase + rr) * KNEI + lane]);
    #pragma unroll
    for (int rr = 0; rr < RPW; rr++)
        yv[rr] = __ldg(&h_refer[mbase + rr]);
    #pragma unroll
    for (int rr = 0; rr < RPW; rr++)
        xv[rr] = __ldg(&h[idxv[rr]]);

    // ================= prologue (once per block) =================
    float r = 0.f, v0, v1, v2, v3, v4, v5, cw1, cw2;
    float pw, pb, pwr, pbr, par;
    if (tid < HDIM) {
        pw  = wl_g[tid];  pb  = bl_g[tid];
        pwr = wr_g[tid];  pbr = br_g[tid];
        par = att_inter[tid];
        float an = att_inter[HDIM + tid];
        if (pw > 0.f) r = pb / pw;
        else          r = (pb > 0.f) ? CUDART_INF_F : -CUDART_INF_F;
        s_rraw[tid] = r;
        v0 = pw * pwr;  v1 = pw * pbr;
        v2 = pb * pwr;  v3 = pb * pbr;
        v4 = pw * an;   v5 = pb * an;
        cw1 = pwr * par; cw2 = pbr * par;
    }
    __syncthreads();
    if (tid < HDIM) {
        // rank via float4 sweeps (stable descending)
        const float4* r4 = (const float4*)s_rraw;
        int rank = 0;
        #pragma unroll
        for (int k4 = 0; k4 < HDIM / 4; k4++) {
            float4 q = r4[k4];
            int k = 4 * k4;
            rank += (q.x > r) || (q.x == r && (k + 0) < tid);
            rank += (q.y > r) || (q.y == r && (k + 1) < tid);
            rank += (q.z > r) || (q.z == r && (k + 2) < tid);
            rank += (q.w > r) || (q.w == r && (k + 3) < tid);
        }
        s_r[rank]     = r;
        s_scat4[rank] = make_float4(v0, v1, v2, v3);
        s_scat2[rank] = make_float2(v4, v5);
        s_wlbl[rank]  = make_float2(pw, pb);
        s_wrbr[rank]  = make_float2(pwr, pbr);
        s_aref[rank]  = par;
        #pragma unroll
        for (int o = 16; o; o >>= 1) {
            cw1 += __shfl_xor_sync(FULLM, cw1, o);
            cw2 += __shfl_xor_sync(FULLM, cw2, o);
        }
        if (lane == 0) { s_cw[warp][0] = cw1; s_cw[warp][1] = cw2; }
    }
    __syncthreads();
    if (tid < HDIM) {
        // inclusive 6-channel scan over the SORTED arrays
        float4 q4 = s_scat4[tid];
        float2 q2 = s_scat2[tid];
        float a0 = q4.x, a1 = q4.y, a2 = q4.z, a3 = q4.w, a4 = q2.x, a5 = q2.y;
        #pragma unroll
        for (int o = 1; o < 32; o <<= 1) {
            float t0 = __shfl_up_sync(FULLM, a0, o);
            float t1 = __shfl_up_sync(FULLM, a1, o);
            float t2 = __shfl_up_sync(FULLM, a2, o);
            float t3 = __shfl_up_sync(FULLM, a3, o);
            float t4 = __shfl_up_sync(FULLM, a4, o);
            float t5 = __shfl_up_sync(FULLM, a5, o);
            if (lane >= o) { a0 += t0; a1 += t1; a2 += t2; a3 += t3; a4 += t4; a5 += t5; }
        }
        if (lane == 31) {
            s_wt[warp][0] = a0; s_wt[warp][1] = a1; s_wt[warp][2] = a2;
            s_wt[warp][3] = a3; s_wt[warp][4] = a4; s_wt[warp][5] = a5;
        }
        s_scat4[tid] = make_float4(a0, a1, a2, a3);
        s_scat2[tid] = make_float2(a4, a5);
    }
    __syncthreads();
    if (tid < HDIM) {
        float o0 = 0.f, o1 = 0.f, o2 = 0.f, o3 = 0.f, o4 = 0.f, o5 = 0.f;
        for (int w = 0; w < warp; w++) {
            o0 += s_wt[w][0]; o1 += s_wt[w][1]; o2 += s_wt[w][2];
            o3 += s_wt[w][3]; o4 += s_wt[w][4]; o5 += s_wt[w][5];
        }
        float4 q4 = s_scat4[tid];
        float2 q2 = s_scat2[tid];
        s_P[tid + 1] = make_float4(q4.x + o0, q4.y + o1, q4.z + o2, q4.w + o3);
        s_F[tid + 1] = make_float2(q2.x + o4, q2.y + o5);
        if (tid == 0) {
            s_P[0] = make_float4(0.f, 0.f, 0.f, 0.f);
            s_F[0] = make_float2(0.f, 0.f);
            s_c12  = make_float2(s_cw[0][0] + s_cw[1][0] + s_cw[2][0] + s_cw[3][0],
                                 s_cw[0][1] + s_cw[1][1] + s_cw[2][1] + s_cw[3][1]);
        }
    }
    __syncthreads();

    // broadcast pivots into registers (levels 0-3 of the search, no LDS chain)
    const float pv127 = s_r[127];
    const float pv63  = s_r[63];
    const float pv31  = s_r[31], pv95  = s_r[95];
    const float pv15  = s_r[15], pv47  = s_r[47], pv79 = s_r[79], pv111 = s_r[111];
    const float c1 = s_c12.x, c2 = s_c12.y;

    // ================= main: RPW rows per warp =================
    #pragma unroll 1
    for (int rr = 0; rr < RPW; rr++) {
        const int m = mbase + rr;
        const float y = yv[rr];
        const float x = xv[rr];

        // c = #{j : r_j > t}, t = -x  (branchless monobound, 8 probes,
        // first 4 from registers)
        const float t = -x;
        int c = (pv63 > t) ? 64 : 0;
        c += ((c ? pv95 : pv31) > t) ? 32 : 0;
        float pv3 = (c & 64) ? ((c & 32) ? pv111 : pv79)
                             : ((c & 32) ? pv47  : pv15);
        c += (pv3 > t) ? 16 : 0;
        c += (s_r[c + 7] > t) ? 8 : 0;
        c += (s_r[c + 3] > t) ? 4 : 0;
        c += (s_r[c + 1] > t) ? 2 : 0;
        c += (s_r[c]     > t) ? 1 : 0;
        c = (pv127 > t) ? 128 : c;          // all-active case

        float2 F = s_F[c];
        float f = fmaf(x, F.x, F.y);        // nei_emb . a_nei

        float gp, lr;
        if (y >= 0.f) {
            // hr_j = y*wr_j + br_j exactly -> row-independent tables
            gp = fmaf(y, c1, c2);
            float4 P = s_P[c];
            lr = fmaf(x, fmaf(y, P.x, P.y), fmaf(y, P.z, P.w));
        } else {
            // fallback: 3-channel warp scan (wl*hr, bl*hr, gp)
            float a[4], b[4];
            float gpl = 0.f;
            #pragma unroll
            for (int i = 0; i < 4; i++) {
                int j = lane * 4 + i;
                float2 u = s_wrbr[j];
                float hr = fmaxf(fmaf(y, u.x, u.y), 0.f);
                gpl = fmaf(hr, s_aref[j], gpl);
                float2 w2 = s_wlbl[j];
                a[i] = w2.x * hr;
                b[i] = w2.y * hr;
            }
            a[1] += a[0]; a[2] += a[1]; a[3] += a[2];
            b[1] += b[0]; b[2] += b[1]; b[3] += b[2];
            float ta = a[3], tb = b[3], tg = gpl;
            #pragma unroll
            for (int o = 1; o < 32; o <<= 1) {
                float va = __shfl_up_sync(FULLM, ta, o);
                float vb = __shfl_up_sync(FULLM, tb, o);
                float vg = __shfl_up_sync(FULLM, tg, o);
                if (lane >= o) { ta += va; tb += vb; tg += vg; }
            }
            gp = __shfl_sync(FULLM, tg, 31);            // full gp sum
            float oa = ta - a[3], ob = tb - b[3];
            if (lane == 0) s_pref[warp][0] = make_float2(0.f, 0.f);
            #pragma unroll
            for (int i = 0; i < 4; i++)
                s_pref[warp][lane * 4 + i + 1] = make_float2(oa + a[i], ob + b[i]);
            __syncwarp();
            float2 p = s_pref[warp][c];
            lr = fmaf(x, p.x, p.y);
            __syncwarp();   // reads done before next row's stores
        }

        float logit = gp + f;
        logit = (logit >= 0.f) ? logit : NEG_SLOPE * logit;

        // warp softmax: exact max via integer redux, fused dual-channel sum
        float mx = warp_max_f32(logit);
        float e  = __expf(logit - mx);
        float s0 = e, s1 = e * lr;
        #pragma unroll
        for (int o = 16; o; o >>= 1) {
            s0 += __shfl_xor_sync(FULLM, s0, o);
            s1 += __shfl_xor_sync(FULLM, s1, o);
        }
        float inv;
        asm("rcp.approx.f32 %0, %1;" : "=f"(inv) : "f"(s0));
        attOut[m * KNEI + lane] = e * inv;
        if (lane == 0) out[m] = fmaxf(s1 * inv, 0.f);
    }
}

// ---------------------------------------------------------------------------
extern "C" void kernel_launch(void* const* d_in, const int* in_sizes, int n_in,
                              void* d_out, int out_size) {
    const int*   nei       = (const int*)  d_in[0];
    const float* h         = (const float*)d_in[1];
    const float* h_refer   = (const float*)d_in[2];
    const float* map_l_w   = (const float*)d_in[3];
    const float* map_l_b   = (const float*)d_in[4];
    const float* map_r_w   = (const float*)d_in[5];
    const float* map_r_b   = (const float*)d_in[6];
    const float* att_inter = (const float*)d_in[7];

    float* out    = (float*)d_out;          // [M]
    float* attOut = out + MROWS;            // [M, K]

    fused_kernel<<<MROWS / (WPB * RPW), 256>>>(nei, h, h_refer,
                                               map_l_w, map_l_b, map_r_w, map_r_b,
                                               att_inter, out, attOut);
}